// round 4
// baseline (speedup 1.0000x reference)
#include <cuda_runtime.h>
#include <cuda_bf16.h>

// FactoredQuantizer: B=8192, M=16, N=256, C=64
//   inputs   [B, M, C] f32
//   codebook [M, N, C] f32
//   out: codes [B, M, C] f32  (+ idx [B, M] as f32 if out_size covers it)
//
// dist(b,m,n) = ||x||^2 - 2 x.c_n + ||c_n||^2 ; argmin over n is independent
// of ||x||^2, so we minimize  c2[n] - 2*dot(x, c_n).
// All arithmetic fp32 (packed f32x2 FFMA = 2 independent fp32 FMAs, exact).

#define BQ 8192
#define MQ 16
#define NQ 256
#define CQ 64

typedef unsigned long long u64;

__device__ __forceinline__ u64 ffma2(u64 a, u64 b, u64 c) {
    u64 d;
    asm("fma.rn.f32x2 %0, %1, %2, %3;" : "=l"(d) : "l"(a), "l"(b), "l"(c));
    return d;
}
__device__ __forceinline__ u64 fadd2(u64 a, u64 b) {
    u64 d;
    asm("add.rn.f32x2 %0, %1, %2;" : "=l"(d) : "l"(a), "l"(b));
    return d;
}

__global__ __launch_bounds__(256, 2)
void fq_kernel(const float* __restrict__ x,
               const float* __restrict__ cb,
               float* __restrict__ out_codes,
               float* __restrict__ out_idx) {
    extern __shared__ float smem[];           // [NQ*CQ] codebook + [NQ] c2
    float* s_cb = smem;
    float* s_c2 = smem + NQ * CQ;

    const int m = blockIdx.y;
    const int t = threadIdx.x;

    // ---- Stage codebook[m] (256x64 f32 = 64 KB) into shared, coalesced f4 ----
    {
        const float4* g  = reinterpret_cast<const float4*>(cb + (size_t)m * NQ * CQ);
        float4*       s4 = reinterpret_cast<float4*>(s_cb);
        #pragma unroll
        for (int i = 0; i < 16; i++)
            s4[t + 256 * i] = g[t + 256 * i];
    }
    __syncthreads();

    // ---- c2[n] = ||c_n||^2 (thread t handles row n=t; one-time cost) ----
    {
        float s = 0.f;
        const float* row = s_cb + t * CQ;
        #pragma unroll
        for (int k = 0; k < CQ; k++) s = fmaf(row[k], row[k], s);
        s_c2[t] = s;
    }
    __syncthreads();

    // ---- Each thread owns one query (b, m): x row in 32 packed-f32x2 regs ----
    const int b = blockIdx.x * 256 + t;
    u64 xv[32];
    {
        const ulonglong2* xg =
            reinterpret_cast<const ulonglong2*>(x + ((size_t)b * MQ + m) * CQ);
        #pragma unroll
        for (int j = 0; j < 16; j++) {
            ulonglong2 v = xg[j];
            xv[2 * j]     = v.x;
            xv[2 * j + 1] = v.y;
        }
    }

    // ---- Main loop over N codes: 32 FFMA2 + reduce + compare per code ----
    float best = 3.402823466e38f;
    int   bidx = 0;
    const ulonglong2* cbase = reinterpret_cast<const ulonglong2*>(s_cb);
    for (int n = 0; n < NQ; n++) {
        const ulonglong2* crow = cbase + n * (CQ / 4);
        u64 a0 = 0ull, a1 = 0ull, a2 = 0ull, a3 = 0ull;  // bits(0.f,0.f)
        #pragma unroll
        for (int j = 0; j < 8; j++) {
            ulonglong2 c0 = crow[2 * j];       // LDS.128, warp-broadcast
            ulonglong2 c1 = crow[2 * j + 1];
            a0 = ffma2(xv[4 * j + 0], c0.x, a0);
            a1 = ffma2(xv[4 * j + 1], c0.y, a1);
            a2 = ffma2(xv[4 * j + 2], c1.x, a2);
            a3 = ffma2(xv[4 * j + 3], c1.y, a3);
        }
        u64 s = fadd2(fadd2(a0, a1), fadd2(a2, a3));
        float lo  = __uint_as_float((unsigned)s);
        float hi  = __uint_as_float((unsigned)(s >> 32));
        float dot = lo + hi;
        float dist = fmaf(-2.0f, dot, s_c2[n]);
        if (dist < best) { best = dist; bidx = n; }   // strict <: first-index tie-break
    }

    // ---- Gather winning code row -> output ----
    {
        float4*       oc  = reinterpret_cast<float4*>(
                                out_codes + ((size_t)b * MQ + m) * CQ);
        const float4* src = reinterpret_cast<const float4*>(s_cb + bidx * CQ);
        #pragma unroll
        for (int j = 0; j < 16; j++) oc[j] = src[j];
    }
    if (out_idx) out_idx[(size_t)b * MQ + m] = (float)bidx;
}

extern "C" void kernel_launch(void* const* d_in, const int* in_sizes, int n_in,
                              void* d_out, int out_size) {
    const float* x  = (const float*)d_in[0];
    const float* cb = (const float*)d_in[1];
    // Disambiguate by element counts (inputs: 8388608, codebook: 262144)
    if (n_in >= 2 && in_sizes[0] == MQ * NQ * CQ) {
        const float* tmp = x; x = cb; cb = tmp;
    }

    float* out_codes = (float*)d_out;
    float* out_idx   = nullptr;
    const long long codes_elems = (long long)BQ * MQ * CQ;   // 8388608
    if ((long long)out_size >= codes_elems + (long long)BQ * MQ)
        out_idx = out_codes + codes_elems;

    const size_t smem_bytes = (NQ * CQ + NQ) * sizeof(float);  // 66560
    cudaFuncSetAttribute(fq_kernel, cudaFuncAttributeMaxDynamicSharedMemorySize,
                         (int)smem_bytes);

    dim3 grid(BQ / 256, MQ);
    fq_kernel<<<grid, 256, smem_bytes>>>(x, cb, out_codes, out_idx);
}